// round 5
// baseline (speedup 1.0000x reference)
#include <cuda_runtime.h>
#include <cstdint>

// Problem constants (fixed shapes for this problem instance)
#define B_DIM 2048
#define D2    4096      // 2*D = flattened (m,d)
#define H_DIM 32768
#define NTOT  (B_DIM * H_DIM)   // 67108864 activations
#define LIST_CAP 262144

// ------------------- device scratch (static, no allocs) -------------------
__device__ float    g_acts[NTOT];           // 268 MB post-ReLU activations
__device__ unsigned g_hist1[4096];
__device__ unsigned g_hist2[4096];
__device__ unsigned g_hist3[256];
__device__ unsigned g_sel1, g_sel2;
__device__ unsigned g_thresh;               // ordered-key threshold (value bits)
__device__ int      g_rem1, g_rem2, g_r;    // remaining counts; g_r = #eq-to-keep
__device__ int      g_ktotal;
__device__ int      g_list_cnt;
__device__ unsigned g_list_flat[LIST_CAP];
__device__ float    g_list_act[LIST_CAP];
__device__ unsigned char g_drop[LIST_CAP];
__device__ int      g_eq_cnt;
__device__ unsigned g_eq_flat[4096];
__device__ int      g_eq_pos[4096];
__device__ int      g_row_cnt[B_DIM];
__device__ int      g_row_fill[B_DIM];
__device__ int      g_row_off[B_DIM + 1];
__device__ int      g_row_h[LIST_CAP];
__device__ float    g_row_a[LIST_CAP];

// ------------------- init -------------------
__global__ void init_kernel(const int* __restrict__ kptr) {
    int t = blockIdx.x * blockDim.x + threadIdx.x;
    int nthr = gridDim.x * blockDim.x;
    for (int i = t; i < 4096; i += nthr) { g_hist1[i] = 0; g_hist2[i] = 0; }
    for (int i = t; i < 256;  i += nthr) g_hist3[i] = 0;
    for (int i = t; i < B_DIM; i += nthr) { g_row_cnt[i] = 0; g_row_fill[i] = 0; }
    if (t == 0) {
        g_list_cnt = 0;
        g_eq_cnt = 0;
        long long kt = (long long)(*kptr) * (long long)B_DIM;
        if (kt > (long long)NTOT) kt = NTOT;
        if (kt < 1) kt = 1;
        g_ktotal = (int)kt;
    }
}

// ------------------- encoder GEMM: acts = relu(x @ W_enc + b_enc) -------------------
// A: (B_DIM x D2) row-major. W: (D2 x H_DIM) row-major.
// 128x64x16 tile, 256 threads, 8x4 micro tile.
// Accuracy: two-level accumulation — each BK=16 chunk summed in a fresh fp32
// temp (ascending-k fma chain), chunk sums added into the running accumulator.
// This cuts summation error ~4x vs a single 4096-long fma chain (sigma ~3e-8),
// pushing our values much closer to exact than the reference's own rounding,
// to avoid selection swaps at the global top-k boundary.
#define BM 128
#define BN 64
#define BK 16

__global__ __launch_bounds__(256) void gemm_enc(
    const float* __restrict__ A, const float* __restrict__ W,
    const float* __restrict__ bias)
{
    __shared__ float As[BK][BM];
    __shared__ float Bs[BK][BN];

    const int bn = blockIdx.x * BN;
    const int bm = blockIdx.y * BM;
    const int tid = threadIdx.x;
    const int tx = tid & 15;        // 0..15 -> n group (4 cols each)
    const int ty = tid >> 4;        // 0..15 -> m group (8 rows each)

    const float* Ap = A + (size_t)bm * D2;
    const float* Wp = W + bn;

    float sum[8][4];
#pragma unroll
    for (int i = 0; i < 8; i++)
#pragma unroll
        for (int j = 0; j < 4; j++) sum[i][j] = 0.f;

    for (int k0 = 0; k0 < D2; k0 += BK) {
        // Load A tile (BM x BK) -> As[k][m]  (two float4 per thread)
#pragma unroll
        for (int l = 0; l < 2; l++) {
            int f = tid + l * 256;          // 0..511 float4s
            int r = f >> 2;                 // row in tile 0..127
            int c = (f & 3) << 2;           // k offset 0,4,8,12
            float4 v = *(const float4*)(Ap + (size_t)r * D2 + k0 + c);
            As[c + 0][r] = v.x; As[c + 1][r] = v.y;
            As[c + 2][r] = v.z; As[c + 3][r] = v.w;
        }
        // Load B tile (BK x BN) -> Bs[k][n]  (one float4 per thread)
        {
            int r = tid >> 4;               // k row 0..15
            int c = (tid & 15) << 2;        // n offset
            *(float4*)(&Bs[r][c]) = *(const float4*)(Wp + (size_t)(k0 + r) * H_DIM + c);
        }
        __syncthreads();

        float chunk[8][4];
#pragma unroll
        for (int i = 0; i < 8; i++)
#pragma unroll
            for (int j = 0; j < 4; j++) chunk[i][j] = 0.f;

#pragma unroll
        for (int kk = 0; kk < BK; kk++) {
            float a[8], b[4];
            *(float4*)(a)     = *(const float4*)(&As[kk][ty * 8]);
            *(float4*)(a + 4) = *(const float4*)(&As[kk][ty * 8 + 4]);
            *(float4*)(b)     = *(const float4*)(&Bs[kk][tx * 4]);
#pragma unroll
            for (int i = 0; i < 8; i++)
#pragma unroll
                for (int j = 0; j < 4; j++)
                    chunk[i][j] = fmaf(a[i], b[j], chunk[i][j]);
        }

#pragma unroll
        for (int i = 0; i < 8; i++)
#pragma unroll
            for (int j = 0; j < 4; j++) sum[i][j] += chunk[i][j];

        __syncthreads();
    }

    // epilogue: + bias, relu, store
    float bb[4];
#pragma unroll
    for (int j = 0; j < 4; j++) bb[j] = bias[bn + tx * 4 + j];

#pragma unroll
    for (int i = 0; i < 8; i++) {
        int r = bm + ty * 8 + i;
        float4 o;
        o.x = fmaxf(sum[i][0] + bb[0], 0.f);
        o.y = fmaxf(sum[i][1] + bb[1], 0.f);
        o.z = fmaxf(sum[i][2] + bb[2], 0.f);
        o.w = fmaxf(sum[i][3] + bb[3], 0.f);
        *(float4*)(&g_acts[(size_t)r * H_DIM + bn + tx * 4]) = o;
    }
}

// ------------------- radix select (3 passes: 12 + 12 + 8 bits) -------------------
// acts >= 0 so float bits are order-preserving unsigned keys.

__global__ void hist_pass1(int n4) {
    __shared__ unsigned sh[4096];
    for (int i = threadIdx.x; i < 4096; i += blockDim.x) sh[i] = 0;
    __syncthreads();
    const int lane = threadIdx.x & 31;
    const int stride = gridDim.x * blockDim.x;
    for (int i = blockIdx.x * blockDim.x + threadIdx.x; i < n4; i += stride) {
        float4 v = ((const float4*)g_acts)[i];
        float vals[4] = {v.x, v.y, v.z, v.w};
#pragma unroll
        for (int c = 0; c < 4; c++) {
            int bin = (int)(__float_as_uint(vals[c]) >> 20);
            unsigned m = __match_any_sync(0xffffffffu, bin);
            if (lane == __ffs(m) - 1) atomicAdd(&sh[bin], (unsigned)__popc(m));
        }
    }
    __syncthreads();
    for (int i = threadIdx.x; i < 4096; i += blockDim.x)
        if (sh[i]) atomicAdd(&g_hist1[i], sh[i]);
}

__global__ void select1_kernel() {
    int target = g_ktotal;
    long long cum = 0;
    for (int v = 4095; v >= 0; v--) {
        unsigned c = g_hist1[v];
        if (cum + (long long)c >= (long long)target) {
            g_sel1 = (unsigned)v;
            g_rem1 = target - (int)cum;
            return;
        }
        cum += c;
    }
    g_sel1 = 0; g_rem1 = 1;
}

__global__ void hist_pass2(int n4) {
    __shared__ unsigned sh[4096];
    for (int i = threadIdx.x; i < 4096; i += blockDim.x) sh[i] = 0;
    __syncthreads();
    const unsigned sel1 = g_sel1;
    const int lane = threadIdx.x & 31;
    const int stride = gridDim.x * blockDim.x;
    for (int i = blockIdx.x * blockDim.x + threadIdx.x; i < n4; i += stride) {
        float4 v = ((const float4*)g_acts)[i];
        float vals[4] = {v.x, v.y, v.z, v.w};
#pragma unroll
        for (int c = 0; c < 4; c++) {
            unsigned key = __float_as_uint(vals[c]);
            int bin = ((key >> 20) == sel1) ? (int)((key >> 8) & 0xFFFu) : -1;
            unsigned m = __match_any_sync(0xffffffffu, bin);
            if (bin >= 0 && lane == __ffs(m) - 1) atomicAdd(&sh[bin], (unsigned)__popc(m));
        }
    }
    __syncthreads();
    for (int i = threadIdx.x; i < 4096; i += blockDim.x)
        if (sh[i]) atomicAdd(&g_hist2[i], sh[i]);
}

__global__ void select2_kernel() {
    int target = g_rem1;
    long long cum = 0;
    for (int v = 4095; v >= 0; v--) {
        unsigned c = g_hist2[v];
        if (cum + (long long)c >= (long long)target) {
            g_sel2 = (unsigned)v;
            g_rem2 = target - (int)cum;
            return;
        }
        cum += c;
    }
    g_sel2 = 0; g_rem2 = 1;
}

__global__ void hist_pass3(int n4) {
    __shared__ unsigned sh[256];
    for (int i = threadIdx.x; i < 256; i += blockDim.x) sh[i] = 0;
    __syncthreads();
    const unsigned prefix20 = (g_sel1 << 12) | g_sel2;
    const int lane = threadIdx.x & 31;
    const int stride = gridDim.x * blockDim.x;
    for (int i = blockIdx.x * blockDim.x + threadIdx.x; i < n4; i += stride) {
        float4 v = ((const float4*)g_acts)[i];
        float vals[4] = {v.x, v.y, v.z, v.w};
#pragma unroll
        for (int c = 0; c < 4; c++) {
            unsigned key = __float_as_uint(vals[c]);
            int bin = ((key >> 8) == prefix20) ? (int)(key & 0xFFu) : -1;
            unsigned m = __match_any_sync(0xffffffffu, bin);
            if (bin >= 0 && lane == __ffs(m) - 1) atomicAdd(&sh[bin], (unsigned)__popc(m));
        }
    }
    __syncthreads();
    for (int i = threadIdx.x; i < 256; i += blockDim.x)
        if (sh[i]) atomicAdd(&g_hist3[i], sh[i]);
}

__global__ void select3_kernel() {
    int target = g_rem2;
    long long cum = 0;
    unsigned prefix = (g_sel1 << 20) | (g_sel2 << 8);
    for (int v = 255; v >= 0; v--) {
        unsigned c = g_hist3[v];
        if (cum + (long long)c >= (long long)target) {
            g_thresh = prefix | (unsigned)v;
            g_r = target - (int)cum;     // # elements == thresh to keep (lowest flat idx first)
            return;
        }
        cum += c;
    }
    g_thresh = prefix; g_r = 1;
}

// ------------------- compaction of key >= thresh -------------------
__global__ void compact_kernel(int n4) {
    const unsigned thresh = g_thresh;
    const int lane = threadIdx.x & 31;
    const int stride = gridDim.x * blockDim.x;
    for (int i = blockIdx.x * blockDim.x + threadIdx.x; i < n4; i += stride) {
        float4 v = ((const float4*)g_acts)[i];
        float vals[4] = {v.x, v.y, v.z, v.w};
#pragma unroll
        for (int c = 0; c < 4; c++) {
            unsigned key = __float_as_uint(vals[c]);
            bool keep = (key >= thresh);
            unsigned m = __ballot_sync(0xffffffffu, keep);
            if (m) {
                int leader = __ffs(m) - 1;
                int base = 0;
                if (lane == leader) base = atomicAdd(&g_list_cnt, __popc(m));
                base = __shfl_sync(0xffffffffu, base, leader);
                if (keep) {
                    int pos = base + __popc(m & ((1u << lane) - 1u));
                    if (pos < LIST_CAP) {
                        g_list_flat[pos] = (unsigned)i * 4u + (unsigned)c;
                        g_list_act[pos]  = vals[c];
                        g_drop[pos] = 0;
                    }
                }
            }
        }
    }
}

// Resolve ties at threshold: keep g_r of them, lowest flat index first (jax top_k order).
__global__ void eq_resolve_kernel() {
    int cnt = g_list_cnt; if (cnt > LIST_CAP) cnt = LIST_CAP;
    const unsigned thresh = g_thresh;
    for (int i = threadIdx.x; i < cnt; i += blockDim.x) {
        if (__float_as_uint(g_list_act[i]) == thresh) {
            int s = atomicAdd(&g_eq_cnt, 1);
            if (s < 4096) { g_eq_flat[s] = g_list_flat[i]; g_eq_pos[s] = i; }
        }
    }
    __syncthreads();
    if (threadIdx.x == 0) {
        int m = g_eq_cnt; if (m > 4096) m = 4096;
        int r = g_r;
        if (m > r) {
            for (int a = 1; a < m; a++) {       // insertion sort by flat index (m is tiny)
                unsigned f = g_eq_flat[a]; int p = g_eq_pos[a]; int b = a - 1;
                while (b >= 0 && g_eq_flat[b] > f) {
                    g_eq_flat[b + 1] = g_eq_flat[b]; g_eq_pos[b + 1] = g_eq_pos[b]; b--;
                }
                g_eq_flat[b + 1] = f; g_eq_pos[b + 1] = p;
            }
            for (int a = r; a < m; a++) g_drop[g_eq_pos[a]] = 1;
        }
    }
}

__global__ void rowcount_kernel() {
    int cnt = g_list_cnt; if (cnt > LIST_CAP) cnt = LIST_CAP;
    const int stride = gridDim.x * blockDim.x;
    for (int i = blockIdx.x * blockDim.x + threadIdx.x; i < cnt; i += stride)
        if (!g_drop[i]) atomicAdd(&g_row_cnt[g_list_flat[i] >> 15], 1);
}

__global__ void rowscan_kernel() {
    __shared__ int s[2][B_DIM];
    const int t = threadIdx.x;
    for (int i = t; i < B_DIM; i += 1024) s[0][i] = g_row_cnt[i];
    __syncthreads();
    int src = 0;
    for (int off = 1; off < B_DIM; off <<= 1) {
        for (int i = t; i < B_DIM; i += 1024)
            s[1 - src][i] = s[src][i] + (i >= off ? s[src][i - off] : 0);
        src = 1 - src;
        __syncthreads();
    }
    for (int i = t; i < B_DIM; i += 1024) g_row_off[i + 1] = s[src][i];
    if (t == 0) g_row_off[0] = 0;
}

__global__ void scatter_kernel() {
    int cnt = g_list_cnt; if (cnt > LIST_CAP) cnt = LIST_CAP;
    const int stride = gridDim.x * blockDim.x;
    for (int i = blockIdx.x * blockDim.x + threadIdx.x; i < cnt; i += stride) {
        if (!g_drop[i]) {
            unsigned f = g_list_flat[i];
            int b = (int)(f >> 15);
            int pos = g_row_off[b] + atomicAdd(&g_row_fill[b], 1);
            g_row_h[pos] = (int)(f & (H_DIM - 1));
            g_row_a[pos] = g_list_act[i];
        }
    }
}

// ------------------- sparse decode: out[b,:] = sum a*W_dec[h,:] + b_dec -------------------
__global__ __launch_bounds__(512) void decode_kernel(
    const float* __restrict__ Wd, const float* __restrict__ bdec,
    float* __restrict__ out)
{
    const int b = blockIdx.x;
    const int t = threadIdx.x;
    const int beg = g_row_off[b];
    const int n = g_row_off[b + 1] - beg;

    __shared__ int   sh_h[2048];
    __shared__ float sh_a[2048];

    float4 acc0 = *(const float4*)(bdec + t * 4);
    float4 acc1 = *(const float4*)(bdec + 2048 + t * 4);

    if (n <= 2048) {
        int P = 1; while (P < n) P <<= 1;
        for (int i = t; i < P; i += 512) {
            if (i < n) { sh_h[i] = g_row_h[beg + i]; sh_a[i] = g_row_a[beg + i]; }
            else       { sh_h[i] = 0x7fffffff; }
        }
        __syncthreads();
        // bitonic sort by h ascending (deterministic accumulation order)
        for (int kk = 2; kk <= P; kk <<= 1) {
            for (int j = kk >> 1; j > 0; j >>= 1) {
                for (int i = t; i < P; i += 512) {
                    int ixj = i ^ j;
                    if (ixj > i) {
                        bool up = ((i & kk) == 0);
                        int h1 = sh_h[i], h2 = sh_h[ixj];
                        if ((h1 > h2) == up) {
                            sh_h[i] = h2; sh_h[ixj] = h1;
                            float a1 = sh_a[i]; sh_a[i] = sh_a[ixj]; sh_a[ixj] = a1;
                        }
                    }
                }
                __syncthreads();
            }
        }
#pragma unroll 2
        for (int j = 0; j < n; j++) {
            int h = sh_h[j];
            float a = sh_a[j];
            const float* w = Wd + (size_t)h * D2;
            float4 w0 = *(const float4*)(w + t * 4);
            float4 w1 = *(const float4*)(w + 2048 + t * 4);
            acc0.x = fmaf(a, w0.x, acc0.x); acc0.y = fmaf(a, w0.y, acc0.y);
            acc0.z = fmaf(a, w0.z, acc0.z); acc0.w = fmaf(a, w0.w, acc0.w);
            acc1.x = fmaf(a, w1.x, acc1.x); acc1.y = fmaf(a, w1.y, acc1.y);
            acc1.z = fmaf(a, w1.z, acc1.z); acc1.w = fmaf(a, w1.w, acc1.w);
        }
    } else {
        for (int j = beg; j < beg + n; j++) {
            int h = g_row_h[j];
            float a = g_row_a[j];
            const float* w = Wd + (size_t)h * D2;
            float4 w0 = *(const float4*)(w + t * 4);
            float4 w1 = *(const float4*)(w + 2048 + t * 4);
            acc0.x = fmaf(a, w0.x, acc0.x); acc0.y = fmaf(a, w0.y, acc0.y);
            acc0.z = fmaf(a, w0.z, acc0.z); acc0.w = fmaf(a, w0.w, acc0.w);
            acc1.x = fmaf(a, w1.x, acc1.x); acc1.y = fmaf(a, w1.y, acc1.y);
            acc1.z = fmaf(a, w1.z, acc1.z); acc1.w = fmaf(a, w1.w, acc1.w);
        }
    }
    *(float4*)(out + (size_t)b * D2 + t * 4) = acc0;
    *(float4*)(out + (size_t)b * D2 + 2048 + t * 4) = acc1;
}

// ------------------- launch -------------------
extern "C" void kernel_launch(void* const* d_in, const int* in_sizes, int n_in,
                              void* d_out, int out_size)
{
    const float* x      = (const float*)d_in[0];   // (B, 2, D) = (B, D2)
    const float* W_enc  = (const float*)d_in[1];   // (D2, H)
    const float* b_enc  = (const float*)d_in[2];   // (H)
    const float* W_dec  = (const float*)d_in[3];   // (H, D2)
    const float* b_dec  = (const float*)d_in[4];   // (D2)
    const int*   kptr   = (const int*)d_in[5];
    float* out = (float*)d_out;

    const int n4 = NTOT / 4;

    init_kernel<<<32, 256>>>(kptr);

    dim3 ggrid(H_DIM / BN, B_DIM / BM);
    gemm_enc<<<ggrid, 256>>>(x, W_enc, b_enc);

    hist_pass1<<<512, 256>>>(n4);
    select1_kernel<<<1, 1>>>();
    hist_pass2<<<512, 256>>>(n4);
    select2_kernel<<<1, 1>>>();
    hist_pass3<<<512, 256>>>(n4);
    select3_kernel<<<1, 1>>>();

    compact_kernel<<<512, 256>>>(n4);
    eq_resolve_kernel<<<1, 256>>>();
    rowcount_kernel<<<256, 256>>>();
    rowscan_kernel<<<1, 1024>>>();
    scatter_kernel<<<256, 256>>>();

    decode_kernel<<<B_DIM, 512>>>(W_dec, b_dec, out);
}

// round 7
// speedup vs baseline: 2.6611x; 2.6611x over previous
#include <cuda_runtime.h>
#include <cuda_fp16.h>
#include <cstdint>

// Problem constants (fixed shapes for this problem instance)
#define B_DIM 2048
#define D2    4096      // 2*D = flattened (m,d) = K of encode GEMM
#define H_DIM 32768
#define NTOT  (B_DIM * H_DIM)   // 67108864 activations
#define LIST_CAP 262144

// ------------------- device scratch (static, no allocs) -------------------
__device__ float  g_acts[NTOT];             // 268 MB post-ReLU activations
// fp16 2-way splits: X in [b][k] layout, W (x512) in original [k][h] layout
__device__ __half g_X0[B_DIM * D2];
__device__ __half g_X1[B_DIM * D2];
__device__ __half g_W0[(size_t)D2 * H_DIM];
__device__ __half g_W1[(size_t)D2 * H_DIM];

__device__ unsigned g_hist1[4096];
__device__ unsigned g_hist2[4096];
__device__ unsigned g_hist3[256];
__device__ unsigned g_sel1, g_sel2;
__device__ unsigned g_thresh;               // ordered-key threshold (value bits)
__device__ int      g_rem1, g_rem2, g_r;    // remaining counts; g_r = #eq-to-keep
__device__ int      g_ktotal;
__device__ int      g_list_cnt;
__device__ unsigned g_list_flat[LIST_CAP];
__device__ float    g_list_act[LIST_CAP];
__device__ unsigned char g_drop[LIST_CAP];
__device__ int      g_eq_cnt;
__device__ unsigned g_eq_flat[4096];
__device__ int      g_eq_pos[4096];
__device__ int      g_row_cnt[B_DIM];
__device__ int      g_row_fill[B_DIM];
__device__ int      g_row_off[B_DIM + 1];
__device__ int      g_row_h[LIST_CAP];
__device__ float    g_row_a[LIST_CAP];

// ------------------- helpers -------------------
__device__ __forceinline__ uint32_t smem_u32(const void* p) {
    uint32_t a;
    asm("{ .reg .u64 t; cvta.to.shared.u64 t, %1; cvt.u32.u64 %0, t; }" : "=r"(a) : "l"(p));
    return a;
}
__device__ __forceinline__ void cp16(uint32_t dst, const void* src) {
    asm volatile("cp.async.cg.shared.global [%0], [%1], 16;" :: "r"(dst), "l"(src));
}
#define CP_COMMIT() asm volatile("cp.async.commit_group;" ::: "memory")

__device__ __forceinline__ void ldsm4(uint32_t r[4], uint32_t a) {
    asm volatile("ldmatrix.sync.aligned.m8n8.x4.shared.b16 {%0,%1,%2,%3}, [%4];"
                 : "=r"(r[0]), "=r"(r[1]), "=r"(r[2]), "=r"(r[3]) : "r"(a));
}
__device__ __forceinline__ void ldsm4t(uint32_t r[4], uint32_t a) {
    asm volatile("ldmatrix.sync.aligned.m8n8.x4.trans.shared.b16 {%0,%1,%2,%3}, [%4];"
                 : "=r"(r[0]), "=r"(r[1]), "=r"(r[2]), "=r"(r[3]) : "r"(a));
}
__device__ __forceinline__ void mma16816(float* c, const uint32_t* a, uint32_t b0, uint32_t b1) {
    asm volatile("mma.sync.aligned.m16n8k16.row.col.f32.f16.f16.f32 "
                 "{%0,%1,%2,%3}, {%4,%5,%6,%7}, {%8,%9}, {%0,%1,%2,%3};"
                 : "+f"(c[0]), "+f"(c[1]), "+f"(c[2]), "+f"(c[3])
                 : "r"(a[0]), "r"(a[1]), "r"(a[2]), "r"(a[3]), "r"(b0), "r"(b1));
}

// ------------------- init -------------------
__global__ void init_kernel(const int* __restrict__ kptr) {
    int t = blockIdx.x * blockDim.x + threadIdx.x;
    int nthr = gridDim.x * blockDim.x;
    for (int i = t; i < 4096; i += nthr) { g_hist1[i] = 0; g_hist2[i] = 0; }
    for (int i = t; i < 256;  i += nthr) g_hist3[i] = 0;
    for (int i = t; i < B_DIM; i += nthr) { g_row_cnt[i] = 0; g_row_fill[i] = 0; }
    if (t == 0) {
        g_list_cnt = 0;
        g_eq_cnt = 0;
        long long kt = (long long)(*kptr) * (long long)B_DIM;
        if (kt > (long long)NTOT) kt = NTOT;
        if (kt < 1) kt = 1;
        g_ktotal = (int)kt;
    }
}

// ------------------- fp16 2-way splits -------------------
__device__ __forceinline__ void split2(float a, __half& h0, __half& h1) {
    h0 = __float2half_rn(a);
    h1 = __float2half_rn(a - __half2float(h0));
}
__device__ __forceinline__ unsigned packh2(__half a, __half b) {
    return (unsigned)__half_as_ushort(a) | ((unsigned)__half_as_ushort(b) << 16);
}

__global__ void split_x_kernel(const float* __restrict__ x) {
    int idx = blockIdx.x * blockDim.x + threadIdx.x;     // one per 4 floats
    float4 v = ((const float4*)x)[idx];
    __half a0, a1, b0, b1, c0, c1, d0, d1;
    split2(v.x, a0, a1); split2(v.y, b0, b1);
    split2(v.z, c0, c1); split2(v.w, d0, d1);
    uint2 o0 = { packh2(a0, b0), packh2(c0, d0) };
    uint2 o1 = { packh2(a1, b1), packh2(c1, d1) };
    ((uint2*)g_X0)[idx] = o0;
    ((uint2*)g_X1)[idx] = o1;
}

// W scaled by 512 (exact power of 2) so the residual split stays out of fp16
// subnormals; epilogue multiplies by 1/512.
__global__ void split_w_kernel(const float* __restrict__ W) {
    size_t idx = (size_t)blockIdx.x * blockDim.x + threadIdx.x;  // one per 4 floats
    float4 v = ((const float4*)W)[idx];
    v.x *= 512.f; v.y *= 512.f; v.z *= 512.f; v.w *= 512.f;
    __half a0, a1, b0, b1, c0, c1, d0, d1;
    split2(v.x, a0, a1); split2(v.y, b0, b1);
    split2(v.z, c0, c1); split2(v.w, d0, d1);
    uint2 o0 = { packh2(a0, b0), packh2(c0, d0) };
    uint2 o1 = { packh2(a1, b1), packh2(c1, d1) };
    ((uint2*)g_W0)[idx] = o0;
    ((uint2*)g_W1)[idx] = o1;
}

// ------------------- fp16x4 HMMA encoder GEMM -------------------
// acts[b][h] = relu( (1/512) * sum_splits X_s[b][:] . W_t[:][h] + bias[h] )
// CTA tile 128x128, 8 warps (2x4), warp tile 64x32, K-stage 64, double buffer.
// Passes A0B0 + A0B1 + A1B0 + A1B1 reconstruct the exact fp32 product to ~2^-22.
// Two-level accumulation: chunk over K=256, then into main (sigma ~4e-8).
#define GEMM_SMEM (2 * 65536)

__global__ __launch_bounds__(256) void gemm_fp16x4(const float* __restrict__ bias) {
    extern __shared__ char smem[];
    const uint32_t sb = smem_u32(smem);
    const int tid = threadIdx.x;
    const int wid = tid >> 5, lane = tid & 31;
    const int bm = blockIdx.x * 128, bn = blockIdx.y * 128;
    const int wm = (wid & 1) * 64, wn = (wid >> 1) * 32;

    // cp.async plan: 16 x 16B chunks per thread per stage.
    // Stage layout: A0 @0 (128m x 64k, 128B rows), A1 @16K, B0 @32K (64k x 128n,
    // 256B rows), B1 @48K. Swizzle: chunk XOR (row&7)*16 for conflict-free ldmatrix.
    uint32_t sdst[16];
    const char* gsrc[16];
#pragma unroll
    for (int l = 0; l < 16; l++) {
        int f = tid + l * 256;
        int reg = f >> 10;          // 0:A0 1:A1 2:B0 3:B1
        int idx = f & 1023;
        if (reg < 2) {
            int m = idx >> 3, kc = idx & 7;
            sdst[l] = (uint32_t)reg * 16384u + (uint32_t)m * 128u +
                      (uint32_t)((kc * 16) ^ ((m & 7) * 16));
            const __half* base = reg ? g_X1 : g_X0;
            gsrc[l] = (const char*)(base + (size_t)(bm + m) * D2 + kc * 8);
        } else {
            int k = idx >> 4, nc = idx & 15;
            sdst[l] = (uint32_t)reg * 16384u + (uint32_t)k * 256u +
                      (uint32_t)((nc * 16) ^ ((k & 7) * 16));
            const __half* base = (reg == 3) ? g_W1 : g_W0;
            gsrc[l] = (const char*)(base + (size_t)k * H_DIM + bn + nc * 8);
        }
    }

    float mainacc[16][4], chunk[16][4];
#pragma unroll
    for (int t = 0; t < 16; t++)
#pragma unroll
        for (int j = 0; j < 4; j++) { mainacc[t][j] = 0.f; chunk[t][j] = 0.f; }

    // ldmatrix lane geometry: matrix j = lane>>3; row-in-matrix i = lane&7
    const int li = lane & 7;
    const int jlo = (lane >> 3) & 1;
    const int jhi = lane >> 4;              // 0..1
    const uint32_t xr = (uint32_t)(li * 16);

    // prologue: stage 0 -> buf0
#pragma unroll
    for (int l = 0; l < 16; l++) cp16(sb + sdst[l], gsrc[l]);
    CP_COMMIT();
#pragma unroll
    for (int l = 0; l < 16; l++) gsrc[l] += (l < 8) ? 128 : 4194304;

    for (int s = 0; s < 64; s++) {
        if (s < 63) {
            const uint32_t bofs = (uint32_t)((s + 1) & 1) * 65536u;
#pragma unroll
            for (int l = 0; l < 16; l++) cp16(sb + bofs + sdst[l], gsrc[l]);
            CP_COMMIT();
#pragma unroll
            for (int l = 0; l < 16; l++) gsrc[l] += (l < 8) ? 128 : 4194304;
            asm volatile("cp.async.wait_group 1;" ::: "memory");
        } else {
            asm volatile("cp.async.wait_group 0;" ::: "memory");
        }
        __syncthreads();

        const uint32_t bb = sb + (uint32_t)(s & 1) * 65536u;
        const uint32_t Abase = bb;
        const uint32_t Bbase = bb + 32768u;

#pragma unroll
        for (int kk = 0; kk < 4; kk++) {
            // B fragments: both splits, 2 ldmatrix.x4.trans each (covers 4 nfrags)
            uint32_t Bf[2][2][4];
            const uint32_t kl = (uint32_t)(kk * 16 + li + jlo * 8);
#pragma unroll
            for (int t = 0; t < 2; t++)
#pragma unroll
                for (int p = 0; p < 2; p++) {
                    uint32_t nbyte = (uint32_t)(wn * 2 + p * 32 + jhi * 16);
                    ldsm4t(Bf[t][p], Bbase + (uint32_t)t * 16384u + kl * 256u + (nbyte ^ xr));
                }
#pragma unroll
            for (int sA = 0; sA < 2; sA++) {
                uint32_t Af[4][4];
                const uint32_t kbyte = (uint32_t)(kk * 32 + jhi * 16);
#pragma unroll
                for (int mf = 0; mf < 4; mf++) {
                    uint32_t ml = (uint32_t)(wm + mf * 16 + li + jlo * 8);
                    ldsm4(Af[mf], Abase + (uint32_t)sA * 16384u + ml * 128u + (kbyte ^ xr));
                }
#pragma unroll
                for (int t = 0; t < 2; t++)
#pragma unroll
                    for (int mf = 0; mf < 4; mf++)
#pragma unroll
                        for (int nf = 0; nf < 4; nf++)
                            mma16816(chunk[mf * 4 + nf], Af[mf],
                                     Bf[t][nf >> 1][(nf & 1) * 2],
                                     Bf[t][nf >> 1][(nf & 1) * 2 + 1]);
            }
        }
        if ((s & 3) == 3) {   // chunk (K=256) -> main
#pragma unroll
            for (int t = 0; t < 16; t++)
#pragma unroll
                for (int j = 0; j < 4; j++) { mainacc[t][j] += chunk[t][j]; chunk[t][j] = 0.f; }
        }
        __syncthreads();
    }

    // epilogue: unscale (1/512 exact), + bias, relu, store
    const float S = 1.f / 512.f;
    const int gr = lane >> 2;
    const int gc = (lane & 3) * 2;
#pragma unroll
    for (int mf = 0; mf < 4; mf++)
#pragma unroll
        for (int nf = 0; nf < 4; nf++) {
            const float* c = mainacc[mf * 4 + nf];
            int row = bm + wm + mf * 16 + gr;
            int col = bn + wn + nf * 8 + gc;
            float2 bv = *(const float2*)(bias + col);
            float2 o0, o1;
            o0.x = fmaxf(fmaf(c[0], S, bv.x), 0.f);
            o0.y = fmaxf(fmaf(c[1], S, bv.y), 0.f);
            o1.x = fmaxf(fmaf(c[2], S, bv.x), 0.f);
            o1.y = fmaxf(fmaf(c[3], S, bv.y), 0.f);
            *(float2*)(&g_acts[(size_t)row * H_DIM + col]) = o0;
            *(float2*)(&g_acts[(size_t)(row + 8) * H_DIM + col]) = o1;
        }
}

// ------------------- radix select (3 passes: 12 + 12 + 8 bits) -------------------
// acts >= 0 so float bits are order-preserving unsigned keys.

__global__ void hist_pass1(int n4) {
    __shared__ unsigned sh[4096];
    for (int i = threadIdx.x; i < 4096; i += blockDim.x) sh[i] = 0;
    __syncthreads();
    const int lane = threadIdx.x & 31;
    const int stride = gridDim.x * blockDim.x;
    for (int i = blockIdx.x * blockDim.x + threadIdx.x; i < n4; i += stride) {
        float4 v = ((const float4*)g_acts)[i];
        float vals[4] = {v.x, v.y, v.z, v.w};
#pragma unroll
        for (int c = 0; c < 4; c++) {
            int bin = (int)(__float_as_uint(vals[c]) >> 20);
            unsigned m = __match_any_sync(0xffffffffu, bin);
            if (lane == __ffs(m) - 1) atomicAdd(&sh[bin], (unsigned)__popc(m));
        }
    }
    __syncthreads();
    for (int i = threadIdx.x; i < 4096; i += blockDim.x)
        if (sh[i]) atomicAdd(&g_hist1[i], sh[i]);
}

__global__ void hist_pass2(int n4) {
    __shared__ unsigned sh[4096];
    for (int i = threadIdx.x; i < 4096; i += blockDim.x) sh[i] = 0;
    __syncthreads();
    const unsigned sel1 = g_sel1;
    const int lane = threadIdx.x & 31;
    const int stride = gridDim.x * blockDim.x;
    for (int i = blockIdx.x * blockDim.x + threadIdx.x; i < n4; i += stride) {
        float4 v = ((const float4*)g_acts)[i];
        float vals[4] = {v.x, v.y, v.z, v.w};
#pragma unroll
        for (int c = 0; c < 4; c++) {
            unsigned key = __float_as_uint(vals[c]);
            int bin = ((key >> 20) == sel1) ? (int)((key >> 8) & 0xFFFu) : -1;
            unsigned m = __match_any_sync(0xffffffffu, bin);
            if (bin >= 0 && lane == __ffs(m) - 1) atomicAdd(&sh[bin], (unsigned)__popc(m));
        }
    }
    __syncthreads();
    for (int i = threadIdx.x; i < 4096; i += blockDim.x)
        if (sh[i]) atomicAdd(&g_hist2[i], sh[i]);
}

__global__ void hist_pass3(int n4) {
    __shared__ unsigned sh[256];
    for (int i = threadIdx.x; i < 256; i += blockDim.x) sh[i] = 0;
    __syncthreads();
    const unsigned prefix20 = (g_sel1 << 12) | g_sel2;
    const int lane = threadIdx.x & 31;
    const int stride = gridDim.x * blockDim.x;
    for (int i = blockIdx.x * blockDim.x + threadIdx.x; i < n4; i += stride) {
        float4 v = ((const float4*)g_acts)[i];
        float vals[4] = {v.x, v.y, v.z, v.w};
#pragma unroll
        for (int c = 0; c < 4; c++) {
            unsigned key = __float_as_uint(vals[c]);
            int bin = ((key >> 8) == prefix20) ? (int)(key & 0xFFu) : -1;
            unsigned m = __match_any_sync(0xffffffffu, bin);
            if (bin >= 0 && lane == __ffs(m) - 1) atomicAdd(&sh[bin], (unsigned)__popc(m));
        }
    }
    __syncthreads();
    for (int i = threadIdx.x; i < 256; i += blockDim.x)
        if (sh[i]) atomicAdd(&g_hist3[i], sh[i]);
}

// Parallel select: suffix-sum the histogram, find cut bin + remainder.
// hist chosen INSIDE the kernel (passing __device__ symbols from host is UB).
__global__ void select_par(int nb, int mode) {
    __shared__ unsigned S[4096];
    const int t = threadIdx.x;      // 1024 threads
    const unsigned* hist = (mode == 0) ? g_hist1 : (mode == 1) ? g_hist2 : g_hist3;
    const int target = (mode == 0) ? g_ktotal : (mode == 1 ? g_rem1 : g_rem2);
    for (int i = t; i < nb; i += 1024) S[i] = hist[i];
    __syncthreads();
    for (int off = 1; off < nb; off <<= 1) {
        unsigned add[4]; int cnt = 0;
        for (int i = t; i < nb; i += 1024) add[cnt++] = (i + off < nb) ? S[i + off] : 0u;
        __syncthreads();
        cnt = 0;
        for (int i = t; i < nb; i += 1024) S[i] += add[cnt++];
        __syncthreads();
    }
    for (int i = t; i < nb; i += 1024) {
        long long Sv = (long long)S[i];
        long long Sn = (i + 1 < nb) ? (long long)S[i + 1] : 0;
        if (Sv >= (long long)target && (i == nb - 1 || Sn < (long long)target)) {
            int rem = target - (int)Sn;
            if (mode == 0)      { g_sel1 = (unsigned)i; g_rem1 = rem; }
            else if (mode == 1) { g_sel2 = (unsigned)i; g_rem2 = rem; }
            else { g_thresh = (g_sel1 << 20) | (g_sel2 << 8) | (unsigned)i; g_r = rem; }
        }
    }
}

// ------------------- compaction of key >= thresh -------------------
__global__ void compact_kernel(int n4) {
    const unsigned thresh = g_thresh;
    const int lane = threadIdx.x & 31;
    const int stride = gridDim.x * blockDim.x;
    for (int i = blockIdx.x * blockDim.x + threadIdx.x; i < n4; i += stride) {
        float4 v = ((const float4*)g_acts)[i];
        float vals[4] = {v.x, v.y, v.z, v.w};
#pragma unroll
        for (int c = 0; c < 4; c++) {
            unsigned key = __float_as_uint(vals[c]);
            bool keep = (key >= thresh);
            unsigned m = __ballot_sync(0xffffffffu, keep);
            if (m) {
                int leader = __ffs(m) - 1;
                int base = 0;
                if (lane == leader) base = atomicAdd(&g_list_cnt, __popc(m));
                base = __shfl_sync(0xffffffffu, base, leader);
                if (keep) {
                    int pos = base + __popc(m & ((1u << lane) - 1u));
                    if (pos < LIST_CAP) {
                        g_list_flat[pos] = (unsigned)i * 4u + (unsigned)c;
                        g_list_act[pos]  = vals[c];
                        g_drop[pos] = 0;
                    }
                }
            }
        }
    }
}

// Resolve ties at threshold: keep g_r of them, lowest flat index first (jax top_k order).
__global__ void eq_resolve_kernel() {
    int cnt = g_list_cnt; if (cnt > LIST_CAP) cnt = LIST_CAP;
    const unsigned thresh = g_thresh;
    for (int i = threadIdx.x; i < cnt; i += blockDim.x) {
        if (__float_as_uint(g_list_act[i]) == thresh) {
            int s = atomicAdd(&g_eq_cnt, 1);
            if (s < 4096) { g_eq_flat[s] = g_list_flat[i]; g_eq_pos[s] = i; }
        }
    }
    __syncthreads();
    if (threadIdx.x == 0) {
        int m = g_eq_cnt; if (m > 4096) m = 4096;
        int r = g_r;
        if (m > r) {
            for (int a = 1; a < m; a++) {       // insertion sort by flat index (m is tiny)
                unsigned f = g_eq_flat[a]; int p = g_eq_pos[a]; int b = a - 1;
                while (b >= 0 && g_eq_flat[b] > f) {
                    g_eq_flat[b + 1] = g_eq_flat[b]; g_eq_pos[b + 1] = g_eq_pos[b]; b--;
                }
                g_eq_flat[b + 1] = f; g_eq_pos[b + 1] = p;
            }
            for (int a = r; a < m; a++) g_drop[g_eq_pos[a]] = 1;
        }
    }
}

__global__ void rowcount_kernel() {
    int cnt = g_list_cnt; if (cnt > LIST_CAP) cnt = LIST_CAP;
    const int stride = gridDim.x * blockDim.x;
    for (int i = blockIdx.x * blockDim.x + threadIdx.x; i < cnt; i += stride)
        if (!g_drop[i]) atomicAdd(&g_row_cnt[g_list_flat[i] >> 15], 1);
}

__global__ void rowscan_kernel() {
    __shared__ int s[2][B_DIM];
    const int t = threadIdx.x;
    for (int i = t; i < B_DIM; i += 1024) s[0][i] = g_row_cnt[i];
    __syncthreads();
    int src = 0;
    for (int off = 1; off < B_DIM; off <<= 1) {
        for (int i = t; i < B_DIM; i += 1024)
            s[1 - src][i] = s[src][i] + (i >= off ? s[src][i - off] : 0);
        src = 1 - src;
        __syncthreads();
    }
    for (int i = t; i < B_DIM; i += 1024) g_row_off[i + 1] = s[src][i];
    if (t == 0) g_row_off[0] = 0;
}

__global__ void scatter_kernel() {
    int cnt = g_list_cnt; if (cnt > LIST_CAP) cnt = LIST_CAP;
    const int stride = gridDim.x * blockDim.x;
    for (int i = blockIdx.x * blockDim.x + threadIdx.x; i < cnt; i += stride) {
        if (!g_drop[i]) {
            unsigned f = g_list_flat[i];
            int b = (int)(f >> 15);
            int pos = g_row_off[b] + atomicAdd(&g_row_fill[b], 1);
            g_row_h[pos] = (int)(f & (H_DIM - 1));
            g_row_a[pos] = g_list_act[i];
        }
    }
}

// ------------------- sparse decode: out[b,:] = sum a*W_dec[h,:] + b_dec -------------------
__global__ __launch_bounds__(512) void decode_kernel(
    const float* __restrict__ Wd, const float* __restrict__ bdec,
    float* __restrict__ out)
{
    const int b = blockIdx.x;
    const int t = threadIdx.x;
    const int beg = g_row_off[b];
    const int n = g_row_off[b + 1] - beg;

    __shared__ int   sh_h[2048];
    __shared__ float sh_a[2048];

    float4 acc0 = *(const float4*)(bdec + t * 4);
    float4 acc1 = *(const float4*)(bdec + 2048 + t * 4);

    if (n <= 2048) {
        int P = 1; while (P < n) P <<= 1;
        for (int i = t; i < P; i += 512) {
            if (i < n) { sh_h[i] = g_row_h[beg + i]; sh_a[i] = g_row_a[beg + i]; }
            else       { sh_h[i] = 0x7fffffff; }
        }
        __syncthreads();
        // bitonic sort by h ascending (deterministic accumulation order)
        for (int kk = 2; kk <= P; kk <<= 1) {
            for (int j = kk >> 1; j > 0; j >>= 1) {
                for (int i = t; i < P; i += 512) {
                    int ixj = i ^ j;
                    if (ixj > i) {
                        bool up = ((i & kk) == 0);
                        int h1 = sh_h[i], h2 = sh_h[ixj];
                        if ((h1 > h2) == up) {
                            sh_h[i] = h2; sh_h[ixj] = h1;
                            float a1 = sh_a[i]; sh_a[i] = sh_a[ixj]; sh_a[ixj] = a1;
                        }
                    }
                }
                __syncthreads();
            }
        }
#pragma unroll 2
        for (int j = 0; j < n; j++) {
            int h = sh_h[j];
            float a = sh_a[j];
            const float* w = Wd + (size_t)h * D2;
            float4 w0 = *(const float4*)(w + t * 4);
            float4 w1 = *(const float4*)(w + 2048 + t * 4);
            acc0.x = fmaf(a, w0.x, acc0.x); acc0.y = fmaf(a, w0.y, acc0.y);
            acc0.z = fmaf(a, w0.z, acc0.z); acc0.w = fmaf(a, w0.w, acc0.w);
            acc1.x = fmaf(a, w1.x, acc1.x); acc1.y = fmaf(a, w1.y, acc1.y);
            acc1.z = fmaf(a, w1.z, acc1.z); acc1.w = fmaf(a, w1.w, acc1.w);
        }
    } else {
        for (int j = beg; j < beg + n; j++) {
            int h = g_row_h[j];
            float a = g_row_a[j];
            const float* w = Wd + (size_t)h * D2;
            float4 w0 = *(const float4*)(w + t * 4);
            float4 w1 = *(const float4*)(w + 2048 + t * 4);
            acc0.x = fmaf(a, w0.x, acc0.x); acc0.y = fmaf(a, w0.y, acc0.y);
            acc0.z = fmaf(a, w0.z, acc0.z); acc0.w = fmaf(a, w0.w, acc0.w);
            acc1.x = fmaf(a, w1.x, acc1.x); acc1.y = fmaf(a, w1.y, acc1.y);
            acc1.z = fmaf(a, w1.z, acc1.z); acc1.w = fmaf(a, w1.w, acc1.w);
        }
    }
    *(float4*)(out + (size_t)b * D2 + t * 4) = acc0;
    *(float4*)(out + (size_t)b * D2 + 2048 + t * 4) = acc1;
}

// ------------------- launch -------------------
extern "C" void kernel_launch(void* const* d_in, const int* in_sizes, int n_in,
                              void* d_out, int out_size)
{
    const float* x      = (const float*)d_in[0];   // (B, 2, D) = (B, D2)
    const float* W_enc  = (const float*)d_in[1];   // (D2, H)
    const float* b_enc  = (const float*)d_in[2];   // (H)
    const float* W_dec  = (const float*)d_in[3];   // (H, D2)
    const float* b_dec  = (const float*)d_in[4];   // (D2)
    const int*   kptr   = (const int*)d_in[5];
    float* out = (float*)d_out;

    const int n4 = NTOT / 4;

    cudaFuncSetAttribute(gemm_fp16x4, cudaFuncAttributeMaxDynamicSharedMemorySize, GEMM_SMEM);

    init_kernel<<<32, 256>>>(kptr);

    split_x_kernel<<<(B_DIM * D2 / 4) / 256, 256>>>(x);
    split_w_kernel<<<(int)(((size_t)D2 * H_DIM / 4) / 256), 256>>>(W_enc);

    // blockIdx.x = M tile (fastest) so each wave's W footprint fits L2
    gemm_fp16x4<<<dim3(B_DIM / 128, H_DIM / 128), 256, GEMM_SMEM>>>(b_enc);

    hist_pass1<<<512, 256>>>(n4);
    select_par<<<1, 1024>>>(4096, 0);
    hist_pass2<<<512, 256>>>(n4);
    select_par<<<1, 1024>>>(4096, 1);
    hist_pass3<<<512, 256>>>(n4);
    select_par<<<1, 1024>>>(256, 2);

    compact_kernel<<<512, 256>>>(n4);
    eq_resolve_kernel<<<1, 256>>>();
    rowcount_kernel<<<256, 256>>>();
    rowscan_kernel<<<1, 1024>>>();
    scatter_kernel<<<256, 256>>>();

    decode_kernel<<<B_DIM, 512>>>(W_dec, b_dec, out);
}

// round 9
// speedup vs baseline: 3.4342x; 1.2905x over previous
#include <cuda_runtime.h>
#include <cuda_fp16.h>
#include <cstdint>

// Problem constants (fixed shapes for this problem instance)
#define B_DIM 2048
#define D2    4096      // 2*D = flattened (m,d) = K of encode GEMM
#define H_DIM 32768
#define NTOT  (B_DIM * H_DIM)   // 67108864 activations
#define LIST_CAP 393216

// ------------------- device scratch (static, no allocs) -------------------
__device__ float  g_acts[NTOT];             // 268 MB post-ReLU activations
// fp16 2-way splits: X in [b][k] layout, W (x512) in original [k][h] layout
__device__ __half g_X0[B_DIM * D2];
__device__ __half g_X1[B_DIM * D2];
__device__ __half g_W0[(size_t)D2 * H_DIM];
__device__ __half g_W1[(size_t)D2 * H_DIM];

__device__ unsigned g_hist1[4096];
__device__ unsigned g_hist2[4096];
__device__ unsigned g_hist3[256];
__device__ unsigned g_sel1, g_sel2;
__device__ unsigned g_thresh;               // ordered-key threshold (value bits)
__device__ int      g_rem1, g_rem2, g_r;    // remaining counts; g_r = #eq-to-keep
__device__ int      g_ktotal;
__device__ int      g_list_cnt;
__device__ unsigned g_list_flat[LIST_CAP];
__device__ float    g_list_act[LIST_CAP];
__device__ unsigned char g_drop[LIST_CAP];
__device__ int      g_eq_cnt;
__device__ unsigned g_eq_flat[4096];
__device__ int      g_eq_pos[4096];
__device__ int      g_row_cnt[B_DIM];
__device__ int      g_row_fill[B_DIM];
__device__ int      g_row_off[B_DIM + 1];
__device__ int      g_row_h[LIST_CAP];
__device__ float    g_row_a[LIST_CAP];

// ------------------- helpers -------------------
__device__ __forceinline__ uint32_t smem_u32(const void* p) {
    uint32_t a;
    asm("{ .reg .u64 t; cvta.to.shared.u64 t, %1; cvt.u32.u64 %0, t; }" : "=r"(a) : "l"(p));
    return a;
}
__device__ __forceinline__ void cp16(uint32_t dst, const void* src) {
    asm volatile("cp.async.cg.shared.global [%0], [%1], 16;" :: "r"(dst), "l"(src));
}
#define CP_COMMIT() asm volatile("cp.async.commit_group;" ::: "memory")

__device__ __forceinline__ void ldsm4(uint32_t r[4], uint32_t a) {
    asm volatile("ldmatrix.sync.aligned.m8n8.x4.shared.b16 {%0,%1,%2,%3}, [%4];"
                 : "=r"(r[0]), "=r"(r[1]), "=r"(r[2]), "=r"(r[3]) : "r"(a));
}
__device__ __forceinline__ void ldsm4t(uint32_t r[4], uint32_t a) {
    asm volatile("ldmatrix.sync.aligned.m8n8.x4.trans.shared.b16 {%0,%1,%2,%3}, [%4];"
                 : "=r"(r[0]), "=r"(r[1]), "=r"(r[2]), "=r"(r[3]) : "r"(a));
}
__device__ __forceinline__ void mma16816(float* c, const uint32_t* a, uint32_t b0, uint32_t b1) {
    asm volatile("mma.sync.aligned.m16n8k16.row.col.f32.f16.f16.f32 "
                 "{%0,%1,%2,%3}, {%4,%5,%6,%7}, {%8,%9}, {%0,%1,%2,%3};"
                 : "+f"(c[0]), "+f"(c[1]), "+f"(c[2]), "+f"(c[3])
                 : "r"(a[0]), "r"(a[1]), "r"(a[2]), "r"(a[3]), "r"(b0), "r"(b1));
}

// ------------------- init -------------------
__global__ void init_kernel(const int* __restrict__ kptr) {
    int t = blockIdx.x * blockDim.x + threadIdx.x;
    int nthr = gridDim.x * blockDim.x;
    for (int i = t; i < 4096; i += nthr) { g_hist1[i] = 0; g_hist2[i] = 0; }
    for (int i = t; i < 256;  i += nthr) g_hist3[i] = 0;
    for (int i = t; i < B_DIM; i += nthr) { g_row_cnt[i] = 0; g_row_fill[i] = 0; }
    if (t == 0) {
        g_list_cnt = 0;
        g_eq_cnt = 0;
        long long kt = (long long)(*kptr) * (long long)B_DIM;
        if (kt > (long long)NTOT) kt = NTOT;
        if (kt < 1) kt = 1;
        g_ktotal = (int)kt;
    }
}

// ------------------- fp16 2-way splits -------------------
__device__ __forceinline__ void split2(float a, __half& h0, __half& h1) {
    h0 = __float2half_rn(a);
    h1 = __float2half_rn(a - __half2float(h0));
}
__device__ __forceinline__ unsigned packh2(__half a, __half b) {
    return (unsigned)__half_as_ushort(a) | ((unsigned)__half_as_ushort(b) << 16);
}

__global__ void split_x_kernel(const float* __restrict__ x) {
    int idx = blockIdx.x * blockDim.x + threadIdx.x;     // one per 4 floats
    float4 v = ((const float4*)x)[idx];
    __half a0, a1, b0, b1, c0, c1, d0, d1;
    split2(v.x, a0, a1); split2(v.y, b0, b1);
    split2(v.z, c0, c1); split2(v.w, d0, d1);
    uint2 o0 = { packh2(a0, b0), packh2(c0, d0) };
    uint2 o1 = { packh2(a1, b1), packh2(c1, d1) };
    ((uint2*)g_X0)[idx] = o0;
    ((uint2*)g_X1)[idx] = o1;
}

// W scaled by 512 (exact power of 2) so the residual split stays out of fp16
// subnormals; epilogue multiplies by 1/512.
__global__ void split_w_kernel(const float* __restrict__ W) {
    size_t idx = (size_t)blockIdx.x * blockDim.x + threadIdx.x;  // one per 4 floats
    float4 v = ((const float4*)W)[idx];
    v.x *= 512.f; v.y *= 512.f; v.z *= 512.f; v.w *= 512.f;
    __half a0, a1, b0, b1, c0, c1, d0, d1;
    split2(v.x, a0, a1); split2(v.y, b0, b1);
    split2(v.z, c0, c1); split2(v.w, d0, d1);
    uint2 o0 = { packh2(a0, b0), packh2(c0, d0) };
    uint2 o1 = { packh2(a1, b1), packh2(c1, d1) };
    ((uint2*)g_W0)[idx] = o0;
    ((uint2*)g_W1)[idx] = o1;
}

// ------------------- fp16x3 HMMA encoder GEMM -------------------
// acts[b][h] = relu( (1/512) * (A0B0 + A0B1 + A1B0) + bias[h] )
// (A1B1 omitted: sigma ~1e-9 abs, far below the top-k swap scale.)
// CTA tile 128x128, 8 warps (2x4), warp tile 64x32, K-stage 64, 3-stage pipeline.
// Two-level accumulation: chunk over K=256, then into main (sigma ~4e-8).
// Epilogue also builds the 12-bit radix histogram (fused hist pass 1).
#define GEMM_SMEM (3 * 65536)

__global__ __launch_bounds__(256) void gemm_fp16x3(const float* __restrict__ bias) {
    extern __shared__ char smem[];
    const uint32_t sb = smem_u32(smem);
    const int tid = threadIdx.x;
    const int wid = tid >> 5, lane = tid & 31;
    const int bm = blockIdx.x * 128, bn = blockIdx.y * 128;
    const int wm = (wid & 1) * 64, wn = (wid >> 1) * 32;

    // cp.async plan: 16 x 16B chunks per thread per stage.
    // Stage layout: A0 @0 (128m x 64k, 128B rows), A1 @16K, B0 @32K (64k x 128n,
    // 256B rows), B1 @48K. Swizzle: chunk XOR (row&7)*16 for conflict-free ldmatrix.
    uint32_t sdst[16];
    const char* gsrc[16];
#pragma unroll
    for (int l = 0; l < 16; l++) {
        int f = tid + l * 256;
        int reg = f >> 10;          // 0:A0 1:A1 2:B0 3:B1
        int idx = f & 1023;
        if (reg < 2) {
            int m = idx >> 3, kc = idx & 7;
            sdst[l] = (uint32_t)reg * 16384u + (uint32_t)m * 128u +
                      (uint32_t)((kc * 16) ^ ((m & 7) * 16));
            const __half* base = reg ? g_X1 : g_X0;
            gsrc[l] = (const char*)(base + (size_t)(bm + m) * D2 + kc * 8);
        } else {
            int k = idx >> 4, nc = idx & 15;
            sdst[l] = (uint32_t)reg * 16384u + (uint32_t)k * 256u +
                      (uint32_t)((nc * 16) ^ ((k & 7) * 16));
            const __half* base = (reg == 3) ? g_W1 : g_W0;
            gsrc[l] = (const char*)(base + (size_t)k * H_DIM + bn + nc * 8);
        }
    }

    float mainacc[16][4], chunk[16][4];
#pragma unroll
    for (int t = 0; t < 16; t++)
#pragma unroll
        for (int j = 0; j < 4; j++) { mainacc[t][j] = 0.f; chunk[t][j] = 0.f; }

    // ldmatrix lane geometry: matrix j = lane>>3; row-in-matrix i = lane&7
    const int li = lane & 7;
    const int jlo = (lane >> 3) & 1;
    const int jhi = lane >> 4;              // 0..1
    const uint32_t xr = (uint32_t)(li * 16);

    // prologue: stages 0,1
#pragma unroll
    for (int l = 0; l < 16; l++) cp16(sb + sdst[l], gsrc[l]);
    CP_COMMIT();
#pragma unroll
    for (int l = 0; l < 16; l++) gsrc[l] += (l < 8) ? 128 : 4194304;
#pragma unroll
    for (int l = 0; l < 16; l++) cp16(sb + 65536u + sdst[l], gsrc[l]);
    CP_COMMIT();
#pragma unroll
    for (int l = 0; l < 16; l++) gsrc[l] += (l < 8) ? 128 : 4194304;

    for (int s = 0; s < 64; s++) {
        if (s + 2 < 64) {
            const uint32_t bofs = (uint32_t)((s + 2) % 3) * 65536u;
#pragma unroll
            for (int l = 0; l < 16; l++) cp16(sb + bofs + sdst[l], gsrc[l]);
            CP_COMMIT();
#pragma unroll
            for (int l = 0; l < 16; l++) gsrc[l] += (l < 8) ? 128 : 4194304;
            asm volatile("cp.async.wait_group 2;" ::: "memory");
        } else if (s == 62) {
            asm volatile("cp.async.wait_group 1;" ::: "memory");
        } else {
            asm volatile("cp.async.wait_group 0;" ::: "memory");
        }
        __syncthreads();

        const uint32_t bb = sb + (uint32_t)(s % 3) * 65536u;
        const uint32_t Abase = bb;
        const uint32_t Bbase = bb + 32768u;

#pragma unroll
        for (int kk = 0; kk < 4; kk++) {
            // B fragments: both splits, 2 ldmatrix.x4.trans each (covers 4 nfrags)
            uint32_t Bf[2][2][4];
            const uint32_t kl = (uint32_t)(kk * 16 + li + jlo * 8);
#pragma unroll
            for (int t = 0; t < 2; t++)
#pragma unroll
                for (int p = 0; p < 2; p++) {
                    uint32_t nbyte = (uint32_t)(wn * 2 + p * 32 + jhi * 16);
                    ldsm4t(Bf[t][p], Bbase + (uint32_t)t * 16384u + kl * 256u + (nbyte ^ xr));
                }
            const uint32_t kbyte = (uint32_t)(kk * 32 + jhi * 16);
            {   // A0: vs B0 and B1
                uint32_t Af[4][4];
#pragma unroll
                for (int mf = 0; mf < 4; mf++) {
                    uint32_t ml = (uint32_t)(wm + mf * 16 + li + jlo * 8);
                    ldsm4(Af[mf], Abase + ml * 128u + (kbyte ^ xr));
                }
#pragma unroll
                for (int t = 0; t < 2; t++)
#pragma unroll
                    for (int mf = 0; mf < 4; mf++)
#pragma unroll
                        for (int nf = 0; nf < 4; nf++)
                            mma16816(chunk[mf * 4 + nf], Af[mf],
                                     Bf[t][nf >> 1][(nf & 1) * 2],
                                     Bf[t][nf >> 1][(nf & 1) * 2 + 1]);
            }
            {   // A1: vs B0 only (A1B1 dropped)
                uint32_t Af[4][4];
#pragma unroll
                for (int mf = 0; mf < 4; mf++) {
                    uint32_t ml = (uint32_t)(wm + mf * 16 + li + jlo * 8);
                    ldsm4(Af[mf], Abase + 16384u + ml * 128u + (kbyte ^ xr));
                }
#pragma unroll
                for (int mf = 0; mf < 4; mf++)
#pragma unroll
                    for (int nf = 0; nf < 4; nf++)
                        mma16816(chunk[mf * 4 + nf], Af[mf],
                                 Bf[0][nf >> 1][(nf & 1) * 2],
                                 Bf[0][nf >> 1][(nf & 1) * 2 + 1]);
            }
        }
        if ((s & 3) == 3) {   // chunk (K=256) -> main
#pragma unroll
            for (int t = 0; t < 16; t++)
#pragma unroll
                for (int j = 0; j < 4; j++) { mainacc[t][j] += chunk[t][j]; chunk[t][j] = 0.f; }
        }
        __syncthreads();
    }

    // epilogue: unscale (1/512 exact), + bias, relu, store; fused 12-bit hist
    unsigned* hist = (unsigned*)smem;        // smem buffers are dead now
    for (int i = tid; i < 4096; i += 256) hist[i] = 0;
    __syncthreads();

    const float S = 1.f / 512.f;
    const int gr = lane >> 2;
    const int gc = (lane & 3) * 2;
#pragma unroll
    for (int mf = 0; mf < 4; mf++)
#pragma unroll
        for (int nf = 0; nf < 4; nf++) {
            const float* c = mainacc[mf * 4 + nf];
            int row = bm + wm + mf * 16 + gr;
            int col = bn + wn + nf * 8 + gc;
            float2 bv = *(const float2*)(bias + col);
            float2 o0, o1;
            o0.x = fmaxf(fmaf(c[0], S, bv.x), 0.f);
            o0.y = fmaxf(fmaf(c[1], S, bv.y), 0.f);
            o1.x = fmaxf(fmaf(c[2], S, bv.x), 0.f);
            o1.y = fmaxf(fmaf(c[3], S, bv.y), 0.f);
            *(float2*)(&g_acts[(size_t)row * H_DIM + col]) = o0;
            *(float2*)(&g_acts[(size_t)(row + 8) * H_DIM + col]) = o1;
            atomicAdd(&hist[__float_as_uint(o0.x) >> 20], 1u);
            atomicAdd(&hist[__float_as_uint(o0.y) >> 20], 1u);
            atomicAdd(&hist[__float_as_uint(o1.x) >> 20], 1u);
            atomicAdd(&hist[__float_as_uint(o1.y) >> 20], 1u);
        }
    __syncthreads();
    for (int i = tid; i < 4096; i += 256)
        if (hist[i]) atomicAdd(&g_hist1[i], hist[i]);
}

// ------------------- radix select over candidate list -------------------
// acts >= 0 so float bits are order-preserving unsigned keys.

// Parallel select: suffix-sum the histogram, find cut bin + remainder.
// hist chosen INSIDE the kernel (passing __device__ symbols from host is UB).
__global__ void select_par(int nb, int mode) {
    __shared__ unsigned S[4096];
    const int t = threadIdx.x;      // 1024 threads
    const unsigned* hist = (mode == 0) ? g_hist1 : (mode == 1) ? g_hist2 : g_hist3;
    const int target = (mode == 0) ? g_ktotal : (mode == 1 ? g_rem1 : g_rem2);
    for (int i = t; i < nb; i += 1024) S[i] = hist[i];
    __syncthreads();
    for (int off = 1; off < nb; off <<= 1) {
        unsigned add[4]; int cnt = 0;
        for (int i = t; i < nb; i += 1024) add[cnt++] = (i + off < nb) ? S[i + off] : 0u;
        __syncthreads();
        cnt = 0;
        for (int i = t; i < nb; i += 1024) S[i] += add[cnt++];
        __syncthreads();
    }
    for (int i = t; i < nb; i += 1024) {
        long long Sv = (long long)S[i];
        long long Sn = (i + 1 < nb) ? (long long)S[i + 1] : 0;
        if (Sv >= (long long)target && (i == nb - 1 || Sn < (long long)target)) {
            int rem = target - (int)Sn;
            if (mode == 0)      { g_sel1 = (unsigned)i; g_rem1 = rem; }
            else if (mode == 1) { g_sel2 = (unsigned)i; g_rem2 = rem; }
            else { g_thresh = (g_sel1 << 20) | (g_sel2 << 8) | (unsigned)i; g_r = rem; }
        }
    }
}

// Single full-array pass: compact all candidates (top-12-bits >= sel1) into the
// list AND build the pass-2 histogram (12 mid bits within the sel1 bin).
__global__ void cand_compact(int n4) {
    __shared__ unsigned sh[4096];
    for (int i = threadIdx.x; i < 4096; i += blockDim.x) sh[i] = 0;
    __syncthreads();
    const unsigned sel1 = g_sel1;
    const unsigned low = sel1 << 20;
    const int lane = threadIdx.x & 31;
    const int stride = gridDim.x * blockDim.x;
    for (int i = blockIdx.x * blockDim.x + threadIdx.x; i < n4; i += stride) {
        float4 v = ((const float4*)g_acts)[i];
        float vals[4] = {v.x, v.y, v.z, v.w};
#pragma unroll
        for (int c = 0; c < 4; c++) {
            unsigned key = __float_as_uint(vals[c]);
            bool keep = (key >= low);
            unsigned m = __ballot_sync(0xffffffffu, keep);
            if (m) {
                int leader = __ffs(m) - 1;
                int base = 0;
                if (lane == leader) base = atomicAdd(&g_list_cnt, __popc(m));
                base = __shfl_sync(0xffffffffu, base, leader);
                if (keep) {
                    int pos = base + __popc(m & ((1u << lane) - 1u));
                    if (pos < LIST_CAP) {
                        g_list_flat[pos] = (unsigned)i * 4u + (unsigned)c;
                        g_list_act[pos]  = vals[c];
                        g_drop[pos] = 0;
                    }
                }
            }
            if ((key >> 20) == sel1) {
                int bin = (int)((key >> 8) & 0xFFFu);
                unsigned mm = __match_any_sync(__activemask(), bin);
                if ((mm & ((1u << lane) - 1u)) == 0) atomicAdd(&sh[bin], (unsigned)__popc(mm));
            }
        }
    }
    __syncthreads();
    for (int i = threadIdx.x; i < 4096; i += blockDim.x)
        if (sh[i]) atomicAdd(&g_hist2[i], sh[i]);
}

// Pass 3 histogram over the candidate list (tiny: ~200K entries)
__global__ void hist3_list() {
    __shared__ unsigned sh[256];
    for (int i = threadIdx.x; i < 256; i += blockDim.x) sh[i] = 0;
    __syncthreads();
    int cnt = g_list_cnt; if (cnt > LIST_CAP) cnt = LIST_CAP;
    const unsigned prefix20 = (g_sel1 << 12) | g_sel2;
    const int stride = gridDim.x * blockDim.x;
    for (int i = blockIdx.x * blockDim.x + threadIdx.x; i < cnt; i += stride) {
        unsigned key = __float_as_uint(g_list_act[i]);
        if ((key >> 8) == prefix20) atomicAdd(&sh[key & 0xFFu], 1u);
    }
    __syncthreads();
    for (int i = threadIdx.x; i < 256; i += blockDim.x)
        if (sh[i]) atomicAdd(&g_hist3[i], sh[i]);
}

// Drop list entries strictly below the final threshold.
__global__ void mark_below() {
    int cnt = g_list_cnt; if (cnt > LIST_CAP) cnt = LIST_CAP;
    const unsigned thresh = g_thresh;
    const int stride = gridDim.x * blockDim.x;
    for (int i = blockIdx.x * blockDim.x + threadIdx.x; i < cnt; i += stride)
        if (__float_as_uint(g_list_act[i]) < thresh) g_drop[i] = 1;
}

// Resolve ties at threshold: keep g_r of them, lowest flat index first (jax top_k order).
__global__ void eq_resolve_kernel() {
    int cnt = g_list_cnt; if (cnt > LIST_CAP) cnt = LIST_CAP;
    const unsigned thresh = g_thresh;
    for (int i = threadIdx.x; i < cnt; i += blockDim.x) {
        if (__float_as_uint(g_list_act[i]) == thresh) {
            int s = atomicAdd(&g_eq_cnt, 1);
            if (s < 4096) { g_eq_flat[s] = g_list_flat[i]; g_eq_pos[s] = i; }
        }
    }
    __syncthreads();
    if (threadIdx.x == 0) {
        int m = g_eq_cnt; if (m > 4096) m = 4096;
        int r = g_r;
        if (m > r) {
            for (int a = 1; a < m; a++) {       // insertion sort by flat index (m is tiny)
                unsigned f = g_eq_flat[a]; int p = g_eq_pos[a]; int b = a - 1;
                while (b >= 0 && g_eq_flat[b] > f) {
                    g_eq_flat[b + 1] = g_eq_flat[b]; g_eq_pos[b + 1] = g_eq_pos[b]; b--;
                }
                g_eq_flat[b + 1] = f; g_eq_pos[b + 1] = p;
            }
            for (int a = r; a < m; a++) g_drop[g_eq_pos[a]] = 1;
        }
    }
}

__global__ void rowcount_kernel() {
    int cnt = g_list_cnt; if (cnt > LIST_CAP) cnt = LIST_CAP;
    const int stride = gridDim.x * blockDim.x;
    for (int i = blockIdx.x * blockDim.x + threadIdx.x; i < cnt; i += stride)
        if (!g_drop[i]) atomicAdd(&g_row_cnt[g_list_flat[i] >> 15], 1);
}

__global__ void rowscan_kernel() {
    __shared__ int s[2][B_DIM];
    const int t = threadIdx.x;
    for (int i = t; i < B_DIM; i += 1024) s[0][i] = g_row_cnt[i];
    __syncthreads();
    int src = 0;
    for (int off = 1; off < B_DIM; off <<= 1) {
        for (int i = t; i < B_DIM; i += 1024)
            s[1 - src][i] = s[src][i] + (i >= off ? s[src][i - off] : 0);
        src = 1 - src;
        __syncthreads();
    }
    for (int i = t; i < B_DIM; i += 1024) g_row_off[i + 1] = s[src][i];
    if (t == 0) g_row_off[0] = 0;
}

__global__ void scatter_kernel() {
    int cnt = g_list_cnt; if (cnt > LIST_CAP) cnt = LIST_CAP;
    const int stride = gridDim.x * blockDim.x;
    for (int i = blockIdx.x * blockDim.x + threadIdx.x; i < cnt; i += stride) {
        if (!g_drop[i]) {
            unsigned f = g_list_flat[i];
            int b = (int)(f >> 15);
            int pos = g_row_off[b] + atomicAdd(&g_row_fill[b], 1);
            g_row_h[pos] = (int)(f & (H_DIM - 1));
            g_row_a[pos] = g_list_act[i];
        }
    }
}

// ------------------- sparse decode: out[b,:] = sum a*W_dec[h,:] + b_dec -------------------
__global__ __launch_bounds__(512) void decode_kernel(
    const float* __restrict__ Wd, const float* __restrict__ bdec,
    float* __restrict__ out)
{
    const int b = blockIdx.x;
    const int t = threadIdx.x;
    const int beg = g_row_off[b];
    const int n = g_row_off[b + 1] - beg;

    __shared__ int   sh_h[2048];
    __shared__ float sh_a[2048];

    float4 acc0 = *(const float4*)(bdec + t * 4);
    float4 acc1 = *(const float4*)(bdec + 2048 + t * 4);

    if (n <= 2048) {
        int P = 1; while (P < n) P <<= 1;
        for (int i = t; i < P; i += 512) {
            if (i < n) { sh_h[i] = g_row_h[beg + i]; sh_a[i] = g_row_a[beg + i]; }
            else       { sh_h[i] = 0x7fffffff; }
        }
        __syncthreads();
        // bitonic sort by h ascending (deterministic accumulation order)
        for (int kk = 2; kk <= P; kk <<= 1) {
            for (int j = kk >> 1; j > 0; j >>= 1) {
                for (int i = t; i < P; i += 512) {
                    int ixj = i ^ j;
                    if (ixj > i) {
                        bool up = ((i & kk) == 0);
                        int h1 = sh_h[i], h2 = sh_h[ixj];
                        if ((h1 > h2) == up) {
                            sh_h[i] = h2; sh_h[ixj] = h1;
                            float a1 = sh_a[i]; sh_a[i] = sh_a[ixj]; sh_a[ixj] = a1;
                        }
                    }
                }
                __syncthreads();
            }
        }
#pragma unroll 2
        for (int j = 0; j < n; j++) {
            int h = sh_h[j];
            float a = sh_a[j];
            const float* w = Wd + (size_t)h * D2;
            float4 w0 = *(const float4*)(w + t * 4);
            float4 w1 = *(const float4*)(w + 2048 + t * 4);
            acc0.x = fmaf(a, w0.x, acc0.x); acc0.y = fmaf(a, w0.y, acc0.y);
            acc0.z = fmaf(a, w0.z, acc0.z); acc0.w = fmaf(a, w0.w, acc0.w);
            acc1.x = fmaf(a, w1.x, acc1.x); acc1.y = fmaf(a, w1.y, acc1.y);
            acc1.z = fmaf(a, w1.z, acc1.z); acc1.w = fmaf(a, w1.w, acc1.w);
        }
    } else {
        for (int j = beg; j < beg + n; j++) {
            int h = g_row_h[j];
            float a = g_row_a[j];
            const float* w = Wd + (size_t)h * D2;
            float4 w0 = *(const float4*)(w + t * 4);
            float4 w1 = *(const float4*)(w + 2048 + t * 4);
            acc0.x = fmaf(a, w0.x, acc0.x); acc0.y = fmaf(a, w0.y, acc0.y);
            acc0.z = fmaf(a, w0.z, acc0.z); acc0.w = fmaf(a, w0.w, acc0.w);
            acc1.x = fmaf(a, w1.x, acc1.x); acc1.y = fmaf(a, w1.y, acc1.y);
            acc1.z = fmaf(a, w1.z, acc1.z); acc1.w = fmaf(a, w1.w, acc1.w);
        }
    }
    *(float4*)(out + (size_t)b * D2 + t * 4) = acc0;
    *(float4*)(out + (size_t)b * D2 + 2048 + t * 4) = acc1;
}

// ------------------- launch -------------------
extern "C" void kernel_launch(void* const* d_in, const int* in_sizes, int n_in,
                              void* d_out, int out_size)
{
    const float* x      = (const float*)d_in[0];   // (B, 2, D) = (B, D2)
    const float* W_enc  = (const float*)d_in[1];   // (D2, H)
    const float* b_enc  = (const float*)d_in[2];   // (H)
    const float* W_dec  = (const float*)d_in[3];   // (H, D2)
    const float* b_dec  = (const float*)d_in[4];   // (D2)
    const int*   kptr   = (const int*)d_in[5];
    float* out = (float*)d_out;

    const int n4 = NTOT / 4;

    cudaFuncSetAttribute(gemm_fp16x3, cudaFuncAttributeMaxDynamicSharedMemorySize, GEMM_SMEM);

    init_kernel<<<32, 256>>>(kptr);

    split_x_kernel<<<(B_DIM * D2 / 4) / 256, 256>>>(x);
    split_w_kernel<<<(int)(((size_t)D2 * H_DIM / 4) / 256), 256>>>(W_enc);

    // blockIdx.x = M tile (fastest) so each wave's W footprint fits L2
    gemm_fp16x3<<<dim3(B_DIM / 128, H_DIM / 128), 256, GEMM_SMEM>>>(b_enc);

    select_par<<<1, 1024>>>(4096, 0);
    cand_compact<<<512, 256>>>(n4);      // one full pass: list + hist2
    select_par<<<1, 1024>>>(4096, 1);
    hist3_list<<<64, 256>>>();
    select_par<<<1, 1024>>>(256, 2);

    mark_below<<<128, 256>>>();
    eq_resolve_kernel<<<1, 256>>>();
    rowcount_kernel<<<256, 256>>>();
    rowscan_kernel<<<1, 1024>>>();
    scatter_kernel<<<256, 256>>>();

    decode_kernel<<<B_DIM, 512>>>(W_dec, b_dec, out);
}